// round 16
// baseline (speedup 1.0000x reference)
#include <cuda_runtime.h>
#include <cuda_bf16.h>
#include <math.h>
#include <stdint.h>

#define N_NODES 200000
#define D 64
#define H 128
#define TILE 128

// ---------------- device scratch ------------------------------------------
__device__ float g_agg1[(size_t)N_NODES * D];
__device__ float g_agg2[(size_t)N_NODES * D];
__device__ float g_cnt1[N_NODES];
__device__ float g_cnt2[N_NODES];
__device__ float g_z[(size_t)3 * N_NODES * D];
__device__ float g_wpart[3];
// Fragment-packed bf16 weights:
__device__ __align__(16) uint2 g_B1h[3 * 4 * 8 * 32];
__device__ __align__(16) uint2 g_B1l[3 * 4 * 8 * 32];
__device__ __align__(16) uint2 g_B3[2 * 4 * 8 * 32];

// ---------------- SMEM layout (bytes) -------------------------------------
#define SM_XHI   0        // 18432: X hi (row stride 36 words) — reused as z-bf16
#define SM_XLO   18432    // 18432: X lo
#define SM_BIAS  36864    // 192 floats
#define SM_BP1   37632    // 128 floats
#define SM_WP2   38144    // 128 floats
#define SMEM_TOTAL 38656

// ---------------- helpers --------------------------------------------------
__device__ __forceinline__ uint32_t pkhi(float a, float b, float& la, float& lb) {
    __nv_bfloat16 ha = __float2bfloat16_rn(a), hb = __float2bfloat16_rn(b);
    la = a - __bfloat162float(ha);
    lb = b - __bfloat162float(hb);
    return (uint32_t)__bfloat16_as_ushort(ha) | ((uint32_t)__bfloat16_as_ushort(hb) << 16);
}
__device__ __forceinline__ uint32_t pk2(float a, float b) {
    return (uint32_t)__bfloat16_as_ushort(__float2bfloat16_rn(a)) |
           ((uint32_t)__bfloat16_as_ushort(__float2bfloat16_rn(b)) << 16);
}
__device__ __forceinline__ void mma16816(float* d, const uint32_t* a, uint2 b) {
    asm volatile("mma.sync.aligned.m16n8k16.row.col.f32.bf16.bf16.f32 "
                 "{%0,%1,%2,%3}, {%4,%5,%6,%7}, {%8,%9}, {%0,%1,%2,%3};"
                 : "+f"(d[0]), "+f"(d[1]), "+f"(d[2]), "+f"(d[3])
                 : "r"(a[0]), "r"(a[1]), "r"(a[2]), "r"(a[3]), "r"(b.x), "r"(b.y));
}
__device__ __forceinline__ float tanha(float x) {
    float th;
    asm("tanh.approx.f32 %0, %1;" : "=f"(th) : "f"(x));
    return th;
}
__device__ __forceinline__ float elu(float v) {
    float e;
    asm("ex2.approx.f32 %0, %1;" : "=f"(e) : "f"(v * 1.4426950408889634f));
    return (v > 0.f) ? v : (e - 1.f);
}
__device__ __forceinline__ void redv4(float* p, float4 v) {
    asm volatile("red.global.add.v4.f32 [%0], {%1,%2,%3,%4};"
                 :: "l"(p), "f"(v.x), "f"(v.y), "f"(v.z), "f"(v.w) : "memory");
}

// ---------------------------------------------------------------------------
__global__ void k_init(int n,
                       const float* __restrict__ Wid, const float* __restrict__ W1,
                       const float* __restrict__ W2, const float* __restrict__ Wp1) {
    int i = blockIdx.x * blockDim.x + threadIdx.x;
    int tot4 = n * (D / 4);
    if (i < tot4) {
        ((float4*)g_agg1)[i] = make_float4(0.f, 0.f, 0.f, 0.f);
        ((float4*)g_agg2)[i] = make_float4(0.f, 0.f, 0.f, 0.f);
    }
    if (i < n) { g_cnt1[i] = 0.f; g_cnt2[i] = 0.f; }
    if (i < 3) g_wpart[i] = 0.f;

    if (blockIdx.x < 4) {
        int t = blockIdx.x * blockDim.x + threadIdx.x;
        for (int idx = t; idx < 3 * 4 * 8 * 32; idx += 1024) {
            int p = idx >> 10, rem = idx & 1023;
            int ks = rem >> 8, rem2 = rem & 255;
            int nt = rem2 >> 5, lane = rem2 & 31;
            int g4 = lane >> 2, tid = lane & 3;
            int nn2 = nt * 8 + g4;
            int w0 = ks * 8 + tid, w1 = w0 + 4;
            const float* W = (p == 0) ? Wid : (p == 1) ? W1 : W2;
            float a0 = W[(2 * w0) * 64 + nn2],     a1 = W[(2 * w0 + 1) * 64 + nn2];
            float b0 = W[(2 * w1) * 64 + nn2],     b1 = W[(2 * w1 + 1) * 64 + nn2];
            float la0, la1, lb0, lb1;
            uint32_t h0 = pkhi(a0, a1, la0, la1);
            uint32_t h1 = pkhi(b0, b1, lb0, lb1);
            g_B1h[idx] = make_uint2(h0, h1);
            g_B1l[idx] = make_uint2(pk2(la0, la1), pk2(lb0, lb1));
        }
        for (int idx = t; idx < 2 * 4 * 8 * 32; idx += 1024) {
            int hh = idx >> 10, rem = idx & 1023;
            int ks = rem >> 8, rem2 = rem & 255;
            int nt = rem2 >> 5, lane = rem2 & 31;
            int g4 = lane >> 2, tid = lane & 3;
            int nn2 = hh * 64 + nt * 8 + g4;
            int w0 = ks * 8 + tid, w1 = w0 + 4;
            g_B3[idx] = make_uint2(
                pk2(Wp1[(2 * w0) * 128 + nn2], Wp1[(2 * w0 + 1) * 128 + nn2]),
                pk2(Wp1[(2 * w1) * 128 + nn2], Wp1[(2 * w1 + 1) * 128 + nn2]));
        }
    }
}

// ---------------------------------------------------------------------------
// MLP-4 scatter (best so far).
__global__ void k_scatter(const float* __restrict__ h,
                          const int* __restrict__ s1, const int* __restrict__ d1,
                          const int* __restrict__ s2, const int* __restrict__ d2,
                          int E) {
    int t = blockIdx.x * blockDim.x + threadIdx.x;
    int half = (E + 1) >> 1;
    int e = t >> 4;
    int c = t & 15;
    if (e >= half) return;
    int eB = e + half;
    bool hasB = eB < E;

    int s1a = s1[e],  d1a = d1[e];
    int s2a = s2[e],  d2a = d2[e];
    int s1b = hasB ? s1[eB] : 0, d1b = hasB ? d1[eB] : 0;
    int s2b = hasB ? s2[eB] : 0, d2b = hasB ? d2[eB] : 0;

    const float4* h4 = (const float4*)h;
    float4 v1a = h4[(size_t)s1a * 16 + c];
    float4 v2a = h4[(size_t)s2a * 16 + c];
    float4 v1b = h4[(size_t)s1b * 16 + c];
    float4 v2b = h4[(size_t)s2b * 16 + c];

    redv4(g_agg1 + (size_t)d1a * 64 + c * 4, v1a);
    redv4(g_agg2 + (size_t)d2a * 64 + c * 4, v2a);
    if (hasB) {
        redv4(g_agg1 + (size_t)d1b * 64 + c * 4, v1b);
        redv4(g_agg2 + (size_t)d2b * 64 + c * 4, v2b);
    }
    if (c == 0) {
        atomicAdd(g_cnt1 + d1a, 1.0f);
        atomicAdd(g_cnt2 + d2a, 1.0f);
        if (hasB) {
            atomicAdd(g_cnt1 + d1b, 1.0f);
            atomicAdd(g_cnt2 + d2b, 1.0f);
        }
    }
}

// ---------------------------------------------------------------------------
// R13 passA, with ONLY the X-fill changed to warp-private coalesced loads:
// warp w covers its own rows m0..m0+31, lanes striped over 16B chunks
// (each warp LDG.128 covers 512B contiguous -> 4 lines, was 32).
__global__ __launch_bounds__(128, 4)
void k_passA(const float* __restrict__ h,
             const float* __restrict__ bid, const float* __restrict__ b1,
             const float* __restrict__ b2,  const float* __restrict__ bp1,
             const float* __restrict__ wp2, int nn) {
    extern __shared__ unsigned char sm[];
    uint32_t* Xhi = (uint32_t*)(sm + SM_XHI);   // also the z-bf16 tile
    uint32_t* Xlo = (uint32_t*)(sm + SM_XLO);
    float* sbias = (float*)(sm + SM_BIAS);
    float* sbp1  = (float*)(sm + SM_BP1);
    float* swp2  = (float*)(sm + SM_WP2);

    const int t = threadIdx.x;
    const int lid = t & 31, w = t >> 5;
    const int g4 = lid >> 2, tid = lid & 3;
    const int m0 = w * 32;
    const int node0 = blockIdx.x * TILE;

    if (t < 64) { sbias[t] = bid[t]; sbias[64 + t] = b1[t]; sbias[128 + t] = b2[t]; }
    if (t < 128) { sbp1[t] = bp1[t]; swp2[t] = wp2[t]; }
    __syncthreads();

    float pw[3];

    for (int p = 0; p < 3; p++) {
        // ---- warp-private coalesced X fill over rows m0..m0+31 ------------
        {
            const float* basep = (p == 0) ? h : ((p == 1) ? g_agg1 : g_agg2);
            const float* cntp  = (p == 1) ? g_cnt1 : g_cnt2;
#pragma unroll
            for (int j = 0; j < 16; j++) {
                int idx = j * 32 + lid;          // chunk index within 32x16 grid
                int r = m0 + (idx >> 4), c4 = idx & 15;
                int node = node0 + r;
                bool valid = node < nn;
                float4 a = make_float4(0.f, 0.f, 0.f, 0.f);
                float inv = 1.f;
                if (valid) {
                    if (p > 0) {
                        float cv = cntp[node];
                        inv = (cv > 0.f) ? 1.f / cv : 0.f;
                    }
                    a = ((const float4*)(basep + (size_t)node * 64))[c4];
                }
                a.x *= inv; a.y *= inv; a.z *= inv; a.w *= inv;
                float l0, l1, l2, l3;
                uint32_t h0 = pkhi(a.x, a.y, l0, l1);
                uint32_t h1 = pkhi(a.z, a.w, l2, l3);
                *(uint2*)&Xhi[r * 36 + c4 * 2] = make_uint2(h0, h1);
                *(uint2*)&Xlo[r * 36 + c4 * 2] = make_uint2(pk2(l0, l1), pk2(l2, l3));
            }
        }
        __syncwarp();

        // ---- GEMM1: acc[2][8][4] = X @ W^T (split bf16, 3 passes) ---------
        float acc[2][8][4];
#pragma unroll
        for (int mt = 0; mt < 2; mt++)
#pragma unroll
            for (int nt = 0; nt < 8; nt++)
#pragma unroll
                for (int i = 0; i < 4; i++) acc[mt][nt][i] = 0.f;

        const uint2* B1hp = g_B1h + (p * 4) * 256;
        const uint2* B1lp = g_B1l + (p * 4) * 256;
#pragma unroll
        for (int ks = 0; ks < 4; ks++) {
            int kw = ks * 8;
            uint32_t ah[2][4], al[2][4];
#pragma unroll
            for (int mt = 0; mt < 2; mt++) {
                int base = (m0 + mt * 16 + g4) * 36 + kw + tid;
                ah[mt][0] = Xhi[base];       ah[mt][1] = Xhi[base + 288];
                ah[mt][2] = Xhi[base + 4];   ah[mt][3] = Xhi[base + 292];
                al[mt][0] = Xlo[base];       al[mt][1] = Xlo[base + 288];
                al[mt][2] = Xlo[base + 4];   al[mt][3] = Xlo[base + 292];
            }
#pragma unroll
            for (int nt = 0; nt < 8; nt++) {
                uint2 bh = __ldg(&B1hp[(ks * 8 + nt) * 32 + lid]);
                uint2 bl = __ldg(&B1lp[(ks * 8 + nt) * 32 + lid]);
#pragma unroll
                for (int mt = 0; mt < 2; mt++) {
                    mma16816(acc[mt][nt], ah[mt], bh);
                    mma16816(acc[mt][nt], ah[mt], bl);
                    mma16816(acc[mt][nt], al[mt], bh);
                }
            }
        }
        __syncwarp();   // GEMM1 reads of Xhi done before epilogue overwrites

        // ---- epilogue1: bias/ELU, STG z fp32, STS z bf16 (into Xhi) -------
#pragma unroll
        for (int mt = 0; mt < 2; mt++) {
            int r = m0 + mt * 16 + g4;
            int nodeA = node0 + r, nodeB = nodeA + 8;
            bool vA = nodeA < nn, vB = nodeB < nn;
            float2* zA = (float2*)(g_z + ((size_t)p * nn + nodeA) * 64);
            float2* zB = (float2*)(g_z + ((size_t)p * nn + nodeB) * 64);
#pragma unroll
            for (int nt = 0; nt < 8; nt++) {
                int c = nt * 8 + tid * 2;
                float2 bb = *(float2*)&sbias[p * 64 + c];
                float v0 = acc[mt][nt][0] + bb.x;
                float v1 = acc[mt][nt][1] + bb.y;
                float v2 = acc[mt][nt][2] + bb.x;
                float v3 = acc[mt][nt][3] + bb.y;
                if (p > 0) {
                    v0 = elu(v0); v1 = elu(v1); v2 = elu(v2); v3 = elu(v3);
                }
                if (vA) zA[nt * 4 + tid] = make_float2(v0, v1);
                if (vB) zB[nt * 4 + tid] = make_float2(v2, v3);
                Xhi[r * 36 + nt * 4 + tid]       = pk2(v0, v1);
                Xhi[(r + 8) * 36 + nt * 4 + tid] = pk2(v2, v3);
            }
        }
        __syncwarp();

        // ---- GEMM2 (bf16): S = z @ Wp1^T; reduce tanh*wp2 -----------------
        float pacc = 0.f;
#pragma unroll
        for (int hh = 0; hh < 2; hh++) {
            float a2c[2][8][4];
#pragma unroll
            for (int mt = 0; mt < 2; mt++)
#pragma unroll
                for (int nt = 0; nt < 8; nt++)
#pragma unroll
                    for (int i = 0; i < 4; i++) a2c[mt][nt][i] = 0.f;
            const uint2* B3p = g_B3 + (hh * 4) * 256;
#pragma unroll
            for (int ks = 0; ks < 4; ks++) {
                int kw = ks * 8;
                uint32_t a2[2][4];
#pragma unroll
                for (int mt = 0; mt < 2; mt++) {
                    int base = (m0 + mt * 16 + g4) * 36 + kw + tid;
                    a2[mt][0] = Xhi[base];     a2[mt][1] = Xhi[base + 288];
                    a2[mt][2] = Xhi[base + 4]; a2[mt][3] = Xhi[base + 292];
                }
#pragma unroll
                for (int nt = 0; nt < 8; nt++) {
                    uint2 b = __ldg(&B3p[(ks * 8 + nt) * 32 + lid]);
#pragma unroll
                    for (int mt = 0; mt < 2; mt++) mma16816(a2c[mt][nt], a2[mt], b);
                }
            }
#pragma unroll
            for (int mt = 0; mt < 2; mt++) {
                int r = m0 + mt * 16 + g4;
                bool vA = (node0 + r) < nn, vB = (node0 + r + 8) < nn;
#pragma unroll
                for (int nt = 0; nt < 8; nt++) {
                    int c = hh * 64 + nt * 8 + tid * 2;
                    float2 bb = *(float2*)&sbp1[c];
                    float2 ww = *(float2*)&swp2[c];
                    if (vA) pacc += tanha(a2c[mt][nt][0] + bb.x) * ww.x
                                  + tanha(a2c[mt][nt][1] + bb.y) * ww.y;
                    if (vB) pacc += tanha(a2c[mt][nt][2] + bb.x) * ww.x
                                  + tanha(a2c[mt][nt][3] + bb.y) * ww.y;
                }
            }
        }
        pw[p] = pacc;
        __syncwarp();   // GEMM2 reads of Xhi done before next plane's fill
    }

    // ---- warp-reduce pw, one atomic per warp per plane ---------------------
#pragma unroll
    for (int p = 0; p < 3; p++) {
        float v = pw[p];
#pragma unroll
        for (int o = 16; o; o >>= 1) v += __shfl_xor_sync(0xffffffffu, v, o);
        if (lid == 0) atomicAdd(&g_wpart[p], v);
    }
}

// ---------------------------------------------------------------------------
__global__ void k_out(float* __restrict__ out, int n) {
    int t = blockIdx.x * blockDim.x + threadIdx.x;
    int tot = n * 16;
    if (t >= tot) return;
    float fn = (float)n;
    float w0 = g_wpart[0] / fn, w1 = g_wpart[1] / fn, w2 = g_wpart[2] / fn;
    float m = fmaxf(w0, fmaxf(w1, w2));
    float e0 = expf(w0 - m), e1 = expf(w1 - m), e2 = expf(w2 - m);
    float inv = 1.f / (e0 + e1 + e2);
    float b0 = e0 * inv, b1 = e1 * inv, b2 = e2 * inv;
    const float4* z = (const float4*)g_z;
    size_t pl = (size_t)n * 16;
    float4 a = z[t], b = z[pl + t], c = z[2 * pl + t];
    float4 o;
    o.x = b0 * a.x + b1 * b.x + b2 * c.x;
    o.y = b0 * a.y + b1 * b.y + b2 * c.y;
    o.z = b0 * a.z + b1 * b.z + b2 * c.z;
    o.w = b0 * a.w + b1 * b.w + b2 * c.w;
    ((float4*)out)[t] = o;
}

// ---------------------------------------------------------------------------
extern "C" void kernel_launch(void* const* d_in, const int* in_sizes, int n_in,
                              void* d_out, int out_size) {
    const float* h   = (const float*)d_in[0];
    const int*   s1  = (const int*)d_in[1];
    const int*   d1  = (const int*)d_in[2];
    const int*   s2  = (const int*)d_in[3];
    const int*   d2  = (const int*)d_in[4];
    const float* Wid = (const float*)d_in[5];
    const float* bid = (const float*)d_in[6];
    const float* W1  = (const float*)d_in[7];
    const float* b1  = (const float*)d_in[8];
    const float* W2  = (const float*)d_in[9];
    const float* b2  = (const float*)d_in[10];
    const float* Wp1 = (const float*)d_in[11];
    const float* bp1 = (const float*)d_in[12];
    const float* Wp2 = (const float*)d_in[13];

    int n = in_sizes[0] / D;   // 200000
    int E = in_sizes[1];       // 1000000

    cudaFuncSetAttribute(k_passA, cudaFuncAttributeMaxDynamicSharedMemorySize, SMEM_TOTAL);

    int tz = (n * 16 + 255) / 256;
    k_init<<<tz, 256>>>(n, Wid, W1, W2, Wp1);

    long long totS = (long long)((E + 1) >> 1) * 16;
    k_scatter<<<(int)((totS + 255) / 256), 256>>>(h, s1, d1, s2, d2, E);

    k_passA<<<(n + TILE - 1) / TILE, 128, SMEM_TOTAL>>>(h, bid, b1, b2, bp1, Wp2, n);

    k_out<<<(n * 16 + 255) / 256, 256>>>((float*)d_out, n);
}

// round 17
// speedup vs baseline: 1.1799x; 1.1799x over previous
#include <cuda_runtime.h>
#include <cuda_fp16.h>
#include <math.h>
#include <stdint.h>

#define N_NODES 200000
#define D 64
#define H 128
#define TILE 128

// ---------------- device scratch ------------------------------------------
__device__ float g_agg1[(size_t)N_NODES * D];
__device__ float g_agg2[(size_t)N_NODES * D];
__device__ float g_cnt1[N_NODES];
__device__ float g_cnt2[N_NODES];
__device__ float g_z[(size_t)3 * N_NODES * D];
__device__ float g_wpart[3];
// Fragment-packed fp16 weights:
//   g_B1: [3][4][8][32] — W^T single-fp16 fragments for GEMM1
//   g_B3: [2][4][8][32] — Wp1^T fp16 fragments for GEMM2
__device__ __align__(16) uint2 g_B1[3 * 4 * 8 * 32];
__device__ __align__(16) uint2 g_B3[2 * 4 * 8 * 32];

// ---------------- SMEM layout (bytes) -------------------------------------
#define SM_XHI   0        // 18432: X hi fp16 (row stride 36 words) — reused as z
#define SM_XLO   18432    // 18432: X lo fp16
#define SM_BIAS  36864    // 192 floats
#define SM_BP1   37632    // 128 floats
#define SM_WP2   38144    // 128 floats
#define SMEM_TOTAL 38656

// ---------------- helpers --------------------------------------------------
__device__ __forceinline__ uint32_t pk2h(float a, float b) {
    __half2 hh = __floats2half2_rn(a, b);
    return *(uint32_t*)&hh;
}
__device__ __forceinline__ uint32_t pkhih(float a, float b, float& la, float& lb) {
    __half ha = __float2half_rn(a), hb = __float2half_rn(b);
    la = a - __half2float(ha);
    lb = b - __half2float(hb);
    return (uint32_t)__half_as_ushort(ha) | ((uint32_t)__half_as_ushort(hb) << 16);
}
__device__ __forceinline__ void mma16816(float* d, const uint32_t* a, uint2 b) {
    asm volatile("mma.sync.aligned.m16n8k16.row.col.f32.f16.f16.f32 "
                 "{%0,%1,%2,%3}, {%4,%5,%6,%7}, {%8,%9}, {%0,%1,%2,%3};"
                 : "+f"(d[0]), "+f"(d[1]), "+f"(d[2]), "+f"(d[3])
                 : "r"(a[0]), "r"(a[1]), "r"(a[2]), "r"(a[3]), "r"(b.x), "r"(b.y));
}
__device__ __forceinline__ float tanha(float x) {
    float th;
    asm("tanh.approx.f32 %0, %1;" : "=f"(th) : "f"(x));
    return th;
}
__device__ __forceinline__ float elu(float v) {
    float e;
    asm("ex2.approx.f32 %0, %1;" : "=f"(e) : "f"(v * 1.4426950408889634f));
    return (v > 0.f) ? v : (e - 1.f);
}
__device__ __forceinline__ void redv4(float* p, float4 v) {
    asm volatile("red.global.add.v4.f32 [%0], {%1,%2,%3,%4};"
                 :: "l"(p), "f"(v.x), "f"(v.y), "f"(v.z), "f"(v.w) : "memory");
}

// ---------------------------------------------------------------------------
__global__ void k_init(int n,
                       const float* __restrict__ Wid, const float* __restrict__ W1,
                       const float* __restrict__ W2, const float* __restrict__ Wp1) {
    int i = blockIdx.x * blockDim.x + threadIdx.x;
    int tot4 = n * (D / 4);
    if (i < tot4) {
        ((float4*)g_agg1)[i] = make_float4(0.f, 0.f, 0.f, 0.f);
        ((float4*)g_agg2)[i] = make_float4(0.f, 0.f, 0.f, 0.f);
    }
    if (i < n) { g_cnt1[i] = 0.f; g_cnt2[i] = 0.f; }
    if (i < 3) g_wpart[i] = 0.f;

    if (blockIdx.x < 4) {
        int t = blockIdx.x * blockDim.x + threadIdx.x;
        for (int idx = t; idx < 3 * 4 * 8 * 32; idx += 1024) {
            int p = idx >> 10, rem = idx & 1023;
            int ks = rem >> 8, rem2 = rem & 255;
            int nt = rem2 >> 5, lane = rem2 & 31;
            int g4 = lane >> 2, tid = lane & 3;
            int nn2 = nt * 8 + g4;
            int w0 = ks * 8 + tid, w1 = w0 + 4;
            const float* W = (p == 0) ? Wid : (p == 1) ? W1 : W2;
            g_B1[idx] = make_uint2(
                pk2h(W[(2 * w0) * 64 + nn2], W[(2 * w0 + 1) * 64 + nn2]),
                pk2h(W[(2 * w1) * 64 + nn2], W[(2 * w1 + 1) * 64 + nn2]));
        }
        for (int idx = t; idx < 2 * 4 * 8 * 32; idx += 1024) {
            int hh = idx >> 10, rem = idx & 1023;
            int ks = rem >> 8, rem2 = rem & 255;
            int nt = rem2 >> 5, lane = rem2 & 31;
            int g4 = lane >> 2, tid = lane & 3;
            int nn2 = hh * 64 + nt * 8 + g4;
            int w0 = ks * 8 + tid, w1 = w0 + 4;
            g_B3[idx] = make_uint2(
                pk2h(Wp1[(2 * w0) * 128 + nn2], Wp1[(2 * w0 + 1) * 128 + nn2]),
                pk2h(Wp1[(2 * w1) * 128 + nn2], Wp1[(2 * w1 + 1) * 128 + nn2]));
        }
    }
}

// ---------------------------------------------------------------------------
// MLP-4 scatter (best so far).
__global__ void k_scatter(const float* __restrict__ h,
                          const int* __restrict__ s1, const int* __restrict__ d1,
                          const int* __restrict__ s2, const int* __restrict__ d2,
                          int E) {
    int t = blockIdx.x * blockDim.x + threadIdx.x;
    int half = (E + 1) >> 1;
    int e = t >> 4;
    int c = t & 15;
    if (e >= half) return;
    int eB = e + half;
    bool hasB = eB < E;

    int s1a = s1[e],  d1a = d1[e];
    int s2a = s2[e],  d2a = d2[e];
    int s1b = hasB ? s1[eB] : 0, d1b = hasB ? d1[eB] : 0;
    int s2b = hasB ? s2[eB] : 0, d2b = hasB ? d2[eB] : 0;

    const float4* h4 = (const float4*)h;
    float4 v1a = h4[(size_t)s1a * 16 + c];
    float4 v2a = h4[(size_t)s2a * 16 + c];
    float4 v1b = h4[(size_t)s1b * 16 + c];
    float4 v2b = h4[(size_t)s2b * 16 + c];

    redv4(g_agg1 + (size_t)d1a * 64 + c * 4, v1a);
    redv4(g_agg2 + (size_t)d2a * 64 + c * 4, v2a);
    if (hasB) {
        redv4(g_agg1 + (size_t)d1b * 64 + c * 4, v1b);
        redv4(g_agg2 + (size_t)d2b * 64 + c * 4, v2b);
    }
    if (c == 0) {
        atomicAdd(g_cnt1 + d1a, 1.0f);
        atomicAdd(g_cnt2 + d2a, 1.0f);
        if (hasB) {
            atomicAdd(g_cnt1 + d1b, 1.0f);
            atomicAdd(g_cnt2 + d2b, 1.0f);
        }
    }
}

// ---------------------------------------------------------------------------
// R13 passA structure; arithmetic switched to split-fp16 (2-pass GEMM1).
__global__ __launch_bounds__(128, 4)
void k_passA(const float* __restrict__ h,
             const float* __restrict__ bid, const float* __restrict__ b1,
             const float* __restrict__ b2,  const float* __restrict__ bp1,
             const float* __restrict__ wp2, int nn) {
    extern __shared__ unsigned char sm[];
    uint32_t* Xhi = (uint32_t*)(sm + SM_XHI);   // also the z-fp16 tile
    uint32_t* Xlo = (uint32_t*)(sm + SM_XLO);
    float* sbias = (float*)(sm + SM_BIAS);
    float* sbp1  = (float*)(sm + SM_BP1);
    float* swp2  = (float*)(sm + SM_WP2);

    const int t = threadIdx.x;
    const int lid = t & 31, w = t >> 5;
    const int g4 = lid >> 2, tid = lid & 3;
    const int m0 = w * 32;
    const int node0 = blockIdx.x * TILE;

    if (t < 64) { sbias[t] = bid[t]; sbias[64 + t] = b1[t]; sbias[128 + t] = b2[t]; }
    if (t < 128) { sbp1[t] = bp1[t]; swp2[t] = wp2[t]; }
    __syncthreads();

    float pw[3];

    for (int p = 0; p < 3; p++) {
        // ---- X fill: thread t -> row t (64 floats -> fp16 hi/lo) ----------
        {
            int node = node0 + t;
            bool valid = node < nn;
            const float* srcp = h;
            float inv = 1.f;
            if (valid) {
                if (p == 0) {
                    srcp = h + (size_t)node * 64;
                } else {
                    const float* agg = (p == 1) ? g_agg1 : g_agg2;
                    float cv = ((p == 1) ? g_cnt1 : g_cnt2)[node];
                    inv = (cv > 0.f) ? 1.f / cv : 0.f;
                    srcp = agg + (size_t)node * 64;
                }
            }
            const float4* s4 = (const float4*)srcp;
#pragma unroll
            for (int q = 0; q < 8; q++) {
                float4 a0, a1;
                if (valid) { a0 = s4[2 * q]; a1 = s4[2 * q + 1]; }
                else { a0 = make_float4(0.f,0.f,0.f,0.f); a1 = a0; }
                float x[8] = { a0.x*inv, a0.y*inv, a0.z*inv, a0.w*inv,
                               a1.x*inv, a1.y*inv, a1.z*inv, a1.w*inv };
                float l[8];
                uint32_t hu[4], lu[4];
#pragma unroll
                for (int i = 0; i < 4; i++)
                    hu[i] = pkhih(x[2*i], x[2*i+1], l[2*i], l[2*i+1]);
#pragma unroll
                for (int i = 0; i < 4; i++) lu[i] = pk2h(l[2*i], l[2*i+1]);
                *(uint4*)&Xhi[t * 36 + 4 * q] = make_uint4(hu[0], hu[1], hu[2], hu[3]);
                *(uint4*)&Xlo[t * 36 + 4 * q] = make_uint4(lu[0], lu[1], lu[2], lu[3]);
            }
        }
        __syncwarp();

        // ---- GEMM1: acc[2][8][4] = X @ W^T (split fp16, 2 passes) ---------
        float acc[2][8][4];
#pragma unroll
        for (int mt = 0; mt < 2; mt++)
#pragma unroll
            for (int nt = 0; nt < 8; nt++)
#pragma unroll
                for (int i = 0; i < 4; i++) acc[mt][nt][i] = 0.f;

        const uint2* B1p = g_B1 + (p * 4) * 256;
#pragma unroll
        for (int ks = 0; ks < 4; ks++) {
            int kw = ks * 8;
            uint32_t ah[2][4], al[2][4];
#pragma unroll
            for (int mt = 0; mt < 2; mt++) {
                int base = (m0 + mt * 16 + g4) * 36 + kw + tid;
                ah[mt][0] = Xhi[base];       ah[mt][1] = Xhi[base + 288];
                ah[mt][2] = Xhi[base + 4];   ah[mt][3] = Xhi[base + 292];
                al[mt][0] = Xlo[base];       al[mt][1] = Xlo[base + 288];
                al[mt][2] = Xlo[base + 4];   al[mt][3] = Xlo[base + 292];
            }
#pragma unroll
            for (int nt = 0; nt < 8; nt++) {
                uint2 b = __ldg(&B1p[(ks * 8 + nt) * 32 + lid]);
#pragma unroll
                for (int mt = 0; mt < 2; mt++) {
                    mma16816(acc[mt][nt], ah[mt], b);
                    mma16816(acc[mt][nt], al[mt], b);
                }
            }
        }
        __syncwarp();   // GEMM1 reads of Xhi done before epilogue overwrites

        // ---- epilogue1: bias/ELU, STG z fp32, STS z fp16 (into Xhi) -------
#pragma unroll
        for (int mt = 0; mt < 2; mt++) {
            int r = m0 + mt * 16 + g4;
            int nodeA = node0 + r, nodeB = nodeA + 8;
            bool vA = nodeA < nn, vB = nodeB < nn;
            float2* zA = (float2*)(g_z + ((size_t)p * nn + nodeA) * 64);
            float2* zB = (float2*)(g_z + ((size_t)p * nn + nodeB) * 64);
#pragma unroll
            for (int nt = 0; nt < 8; nt++) {
                int c = nt * 8 + tid * 2;
                float2 bb = *(float2*)&sbias[p * 64 + c];
                float v0 = acc[mt][nt][0] + bb.x;
                float v1 = acc[mt][nt][1] + bb.y;
                float v2 = acc[mt][nt][2] + bb.x;
                float v3 = acc[mt][nt][3] + bb.y;
                if (p > 0) {
                    v0 = elu(v0); v1 = elu(v1); v2 = elu(v2); v3 = elu(v3);
                }
                if (vA) zA[nt * 4 + tid] = make_float2(v0, v1);
                if (vB) zB[nt * 4 + tid] = make_float2(v2, v3);
                Xhi[r * 36 + nt * 4 + tid]       = pk2h(v0, v1);
                Xhi[(r + 8) * 36 + nt * 4 + tid] = pk2h(v2, v3);
            }
        }
        __syncwarp();

        // ---- GEMM2 (fp16): S = z @ Wp1^T; reduce tanh*wp2 -----------------
        float pacc = 0.f;
#pragma unroll
        for (int hh = 0; hh < 2; hh++) {
            float a2c[2][8][4];
#pragma unroll
            for (int mt = 0; mt < 2; mt++)
#pragma unroll
                for (int nt = 0; nt < 8; nt++)
#pragma unroll
                    for (int i = 0; i < 4; i++) a2c[mt][nt][i] = 0.f;
            const uint2* B3p = g_B3 + (hh * 4) * 256;
#pragma unroll
            for (int ks = 0; ks < 4; ks++) {
                int kw = ks * 8;
                uint32_t a2[2][4];
#pragma unroll
                for (int mt = 0; mt < 2; mt++) {
                    int base = (m0 + mt * 16 + g4) * 36 + kw + tid;
                    a2[mt][0] = Xhi[base];     a2[mt][1] = Xhi[base + 288];
                    a2[mt][2] = Xhi[base + 4]; a2[mt][3] = Xhi[base + 292];
                }
#pragma unroll
                for (int nt = 0; nt < 8; nt++) {
                    uint2 b = __ldg(&B3p[(ks * 8 + nt) * 32 + lid]);
#pragma unroll
                    for (int mt = 0; mt < 2; mt++) mma16816(a2c[mt][nt], a2[mt], b);
                }
            }
#pragma unroll
            for (int mt = 0; mt < 2; mt++) {
                int r = m0 + mt * 16 + g4;
                bool vA = (node0 + r) < nn, vB = (node0 + r + 8) < nn;
#pragma unroll
                for (int nt = 0; nt < 8; nt++) {
                    int c = hh * 64 + nt * 8 + tid * 2;
                    float2 bb = *(float2*)&sbp1[c];
                    float2 ww = *(float2*)&swp2[c];
                    if (vA) pacc += tanha(a2c[mt][nt][0] + bb.x) * ww.x
                                  + tanha(a2c[mt][nt][1] + bb.y) * ww.y;
                    if (vB) pacc += tanha(a2c[mt][nt][2] + bb.x) * ww.x
                                  + tanha(a2c[mt][nt][3] + bb.y) * ww.y;
                }
            }
        }
        pw[p] = pacc;
        __syncwarp();   // GEMM2 reads of Xhi done before next plane's fill
    }

    // ---- warp-reduce pw, one atomic per warp per plane ---------------------
#pragma unroll
    for (int p = 0; p < 3; p++) {
        float v = pw[p];
#pragma unroll
        for (int o = 16; o; o >>= 1) v += __shfl_xor_sync(0xffffffffu, v, o);
        if (lid == 0) atomicAdd(&g_wpart[p], v);
    }
}

// ---------------------------------------------------------------------------
__global__ void k_out(float* __restrict__ out, int n) {
    int t = blockIdx.x * blockDim.x + threadIdx.x;
    int tot = n * 16;
    if (t >= tot) return;
    float fn = (float)n;
    float w0 = g_wpart[0] / fn, w1 = g_wpart[1] / fn, w2 = g_wpart[2] / fn;
    float m = fmaxf(w0, fmaxf(w1, w2));
    float e0 = expf(w0 - m), e1 = expf(w1 - m), e2 = expf(w2 - m);
    float inv = 1.f / (e0 + e1 + e2);
    float b0 = e0 * inv, b1 = e1 * inv, b2 = e2 * inv;
    const float4* z = (const float4*)g_z;
    size_t pl = (size_t)n * 16;
    float4 a = z[t], b = z[pl + t], c = z[2 * pl + t];
    float4 o;
    o.x = b0 * a.x + b1 * b.x + b2 * c.x;
    o.y = b0 * a.y + b1 * b.y + b2 * c.y;
    o.z = b0 * a.z + b1 * b.z + b2 * c.z;
    o.w = b0 * a.w + b1 * b.w + b2 * c.w;
    ((float4*)out)[t] = o;
}

// ---------------------------------------------------------------------------
extern "C" void kernel_launch(void* const* d_in, const int* in_sizes, int n_in,
                              void* d_out, int out_size) {
    const float* h   = (const float*)d_in[0];
    const int*   s1  = (const int*)d_in[1];
    const int*   d1  = (const int*)d_in[2];
    const int*   s2  = (const int*)d_in[3];
    const int*   d2  = (const int*)d_in[4];
    const float* Wid = (const float*)d_in[5];
    const float* bid = (const float*)d_in[6];
    const float* W1  = (const float*)d_in[7];
    const float* b1  = (const float*)d_in[8];
    const float* W2  = (const float*)d_in[9];
    const float* b2  = (const float*)d_in[10];
    const float* Wp1 = (const float*)d_in[11];
    const float* bp1 = (const float*)d_in[12];
    const float* Wp2 = (const float*)d_in[13];

    int n = in_sizes[0] / D;   // 200000
    int E = in_sizes[1];       // 1000000

    cudaFuncSetAttribute(k_passA, cudaFuncAttributeMaxDynamicSharedMemorySize, SMEM_TOTAL);

    int tz = (n * 16 + 255) / 256;
    k_init<<<tz, 256>>>(n, Wid, W1, W2, Wp1);

    long long totS = (long long)((E + 1) >> 1) * 16;
    k_scatter<<<(int)((totS + 255) / 256), 256>>>(h, s1, d1, s2, d2, E);

    k_passA<<<(n + TILE - 1) / TILE, 128, SMEM_TOTAL>>>(h, bid, b1, b2, bp1, Wp2, n);

    k_out<<<(n * 16 + 255) / 256, 256>>>((float*)d_out, n);
}